// round 11
// baseline (speedup 1.0000x reference)
#include <cuda_runtime.h>
#include <cuda_fp16.h>
#include <math.h>
#include <stdint.h>

// ---------------- problem constants ----------------
#define BB 4
#define TT 4096
#define DD 1024
#define KK 128
#define HH 8
#define KER 4
#define MM 4096          // mlp hidden
#define C2K 256          // 2*K
#define NT (BB*TT)       // 16384 rows

// ---------------- scratch (static device, no allocs) ----------------
__device__ __half g_xn_h[(size_t)NT*DD];     // LN1 out fp16
__device__ __half g_y_h[(size_t)NT*DD];      // LN2 out fp16
__device__ __half g_h1_h[(size_t)NT*MM];     // mlp mid fp16
__device__ __half g_eig_h[(size_t)NT*C2K];   // fp16 copy of eig
__device__ __half g_pe_h[(size_t)NT*C2K];    // fp16 prev_eig
__device__ __half g_sig_h[(size_t)NT*DD];    // sigmoid gate fp16
__device__ float  g_beta0[(size_t)NT*C2K];
__device__ float  g_pm[(size_t)NT*C2K];
__device__ float  g_bR[(size_t)BB*KK*TT];
__device__ float  g_bI[(size_t)BB*KK*TT];
__device__ float  g_cR[(size_t)BB*KK*TT];
__device__ float  g_cI[(size_t)BB*KK*TT];
__device__ float  g_x1[(size_t)NT*DD];
// fp16 weights, packed
#define W_INPROJ  0
#define W_MEMPROJ (W_INPROJ + C2K*DD)
#define W_OUTPROJ (W_MEMPROJ + C2K*C2K)
#define W_GATE    (W_OUTPROJ + DD*C2K)
#define W_MLP1    (W_GATE + DD*DD)
#define W_MLP2    (W_MLP1 + (size_t)MM*DD)
#define W_TOTAL   (W_MLP2 + (size_t)DD*MM)
__device__ __half g_wh[W_TOTAL];

__device__ __forceinline__ float sigmf(float x) { return 1.f / (1.f + __expf(-x)); }
__device__ __forceinline__ uint32_t smem_u32(const void* p) {
    uint32_t a;
    asm("{ .reg .u64 t; cvta.to.shared.u64 t, %1; cvt.u32.u64 %0, t; }" : "=r"(a) : "l"(p));
    return a;
}
__device__ __forceinline__ void cp16(uint32_t s, const void* g) {
    asm volatile("cp.async.cg.shared.global [%0], [%1], 16;" :: "r"(s), "l"(g));
}
__device__ __forceinline__ uint32_t h2u(__half2 h) { return *(uint32_t*)&h; }
__device__ __forceinline__ void ldsm_x4(uint32_t& r0, uint32_t& r1, uint32_t& r2, uint32_t& r3,
                                        uint32_t addr) {
    asm volatile("ldmatrix.sync.aligned.m8n8.x4.shared.b16 {%0,%1,%2,%3}, [%4];"
                 : "=r"(r0), "=r"(r1), "=r"(r2), "=r"(r3) : "r"(addr));
}

// ============================ batched fp32 -> fp16 ============================
struct CvtArgs {
    const float* src[7];
    __half* dst[7];
    int n8[7];
};
__global__ void cvt_all_kernel(CvtArgs a)
{
    const int seg = blockIdx.y;
    const int i = blockIdx.x * blockDim.x + threadIdx.x;
    if (i < a.n8[seg]) {
        const float4* s4 = (const float4*)a.src[seg] + 2 * (size_t)i;
        float4 p = s4[0], q = s4[1];
        uint4 o = {h2u(__floats2half2_rn(p.x, p.y)), h2u(__floats2half2_rn(p.z, p.w)),
                   h2u(__floats2half2_rn(q.x, q.y)), h2u(__floats2half2_rn(q.z, q.w))};
        ((uint4*)a.dst[seg])[i] = o;
    }
}

// ============================ LayerNorm -> fp16 out ============================
__global__ void ten_ln_kernel(const float* __restrict__ x,
                              const float* __restrict__ gw,
                              const float* __restrict__ bw,
                              __half* __restrict__ yh)
{
    const int row = blockIdx.x;
    const int tid = threadIdx.x;
    const float4* xr = (const float4*)(x + (size_t)row * DD);
    float4 v = xr[tid];
    float s = v.x + v.y + v.z + v.w;
    float q = v.x*v.x + v.y*v.y + v.z*v.z + v.w*v.w;
    #pragma unroll
    for (int o = 16; o > 0; o >>= 1) {
        s += __shfl_xor_sync(0xffffffffu, s, o);
        q += __shfl_xor_sync(0xffffffffu, q, o);
    }
    __shared__ float ss[8], sq[8];
    const int w = tid >> 5, l = tid & 31;
    if (l == 0) { ss[w] = s; sq[w] = q; }
    __syncthreads();
    float st = 0.f, qt = 0.f;
    #pragma unroll
    for (int i = 0; i < 8; i++) { st += ss[i]; qt += sq[i]; }
    const float mean = st * (1.f / DD);
    const float var  = qt * (1.f / DD) - mean * mean;
    const float rstd = rsqrtf(var + 1e-5f);
    float4 g4 = ((const float4*)gw)[tid];
    float4 b4 = ((const float4*)bw)[tid];
    float ox = (v.x - mean) * rstd * g4.x + b4.x;
    float oy = (v.y - mean) * rstd * g4.y + b4.y;
    float oz = (v.z - mean) * rstd * g4.z + b4.z;
    float ow = (v.w - mean) * rstd * g4.w + b4.w;
    uint2 ov = {h2u(__floats2half2_rn(ox, oy)), h2u(__floats2half2_rn(oz, ow))};
    ((uint2*)(yh + (size_t)row * DD))[tid] = ov;
}

// ============================ fp16 mma.sync GEMM ============================
// block 128x128, BK=64 halves, 3-stage cp.async ring, 16 warps (4x4),
// warp tile 32x32 (2x4 m16n8k16, 32 acc regs), 2 CTAs/SM = 8 warps/SMSP.
enum { EPI_NONE = 0, EPI_SIG = 1, EPI_GATE = 2, EPI_SILU_H = 3, EPI_BIAS_RES = 4 };

#define ASTR 36                    // b32 per SMEM row (32 data + 4 pad)
#define ROWB (ASTR*4)              // 144 bytes per row
#define A_B32 (128*ASTR)
#define B_B32 (128*ASTR)
#define ST_B32 (A_B32 + B_B32)     // 9216 b32
#define GEMM_SMEM (3*ST_B32*4)     // 110592 B

template<int EPI>
__global__ void __launch_bounds__(512, 2)
mma_gemm(const __half* __restrict__ A, const __half* __restrict__ B, void* Cv,
         int M, int N, int K,
         const float* __restrict__ aux0, const void* __restrict__ aux1,
         const float* __restrict__ aux2)
{
    extern __shared__ uint32_t smu[];
    const uint32_t sm_base = smem_u32(smu);
    const int tid = threadIdx.x;
    const int lane = tid & 31, wid = tid >> 5;
    const int wm = wid >> 2, wn = wid & 3;          // 4 x 4 warp grid
    const int m0 = blockIdx.y * 128, n0 = blockIdx.x * 128;
    const int nchunk = K >> 6;
    const int g = lane >> 2, t = lane & 3;

    const __half* Ag = A + (size_t)m0 * K;
    const __half* Bg = B + (size_t)n0 * K;

    // cp.async geometry: 512 threads; r0 0..63, u 0..7; rows r0 and r0+64
    const int r0 = tid >> 3;
    const int u  = tid & 7;
    const uint32_t cpSmA0 = (uint32_t)(r0 * ASTR + u * 4) * 4;
    const uint32_t cpSmB0 = (uint32_t)(A_B32 + r0 * ASTR + u * 4) * 4;
    const uint32_t cpSmStep = (uint32_t)(64 * ASTR) * 4;

    auto load_stage = [&](int s, int c) {
        const uint32_t sb = sm_base + (uint32_t)(s * ST_B32) * 4;
        const __half* ac = Ag + (size_t)c * 64;
        const __half* bc = Bg + (size_t)c * 64;
        #pragma unroll
        for (int j = 0; j < 2; j++) {
            const int r = r0 + j * 64;
            cp16(sb + cpSmA0 + j * cpSmStep, ac + (size_t)r * K + u * 8);
            cp16(sb + cpSmB0 + j * cpSmStep, bc + (size_t)r * K + u * 8);
        }
        asm volatile("cp.async.commit_group;");
    };

    float acc[2][4][4];
    #pragma unroll
    for (int mi = 0; mi < 2; mi++)
        #pragma unroll
        for (int ni = 0; ni < 4; ni++)
            #pragma unroll
            for (int q = 0; q < 4; q++) acc[mi][ni][q] = 0.f;

    load_stage(0, 0);
    if (1 < nchunk) load_stage(1, 1);

    const uint32_t aOff = (uint32_t)(wm * 32 + (lane & 15)) * ROWB + (uint32_t)(lane >> 4) * 16;
    const uint32_t bOff = (uint32_t)A_B32 * 4 +
        (uint32_t)(wn * 32 + (lane & 7) + ((lane >> 4) & 1) * 8) * ROWB +
        (uint32_t)((lane >> 3) & 1) * 16;

    int stage = 0;
    for (int i = 0; i < nchunk; i++) {
        if (i == nchunk - 1) asm volatile("cp.async.wait_group 0;" ::: "memory");
        else                 asm volatile("cp.async.wait_group 1;" ::: "memory");
        __syncthreads();

        const bool pf = (i + 2 < nchunk);
        int ns = stage + 2; if (ns >= 3) ns -= 3;
        const uint32_t pfSb = sm_base + (uint32_t)(ns * ST_B32) * 4;
        const __half* pfA = Ag + (size_t)(i + 2) * 64 + (size_t)r0 * K + u * 8;
        const __half* pfB = Bg + (size_t)(i + 2) * 64 + (size_t)r0 * K + u * 8;

        const uint32_t stBase = sm_base + (uint32_t)(stage * ST_B32) * 4;
        #pragma unroll
        for (int ks = 0; ks < 4; ks++) {
            const uint32_t kb = (uint32_t)ks * 32;
            uint32_t af[2][4], bf[4][2];
            #pragma unroll
            for (int mi = 0; mi < 2; mi++)
                ldsm_x4(af[mi][0], af[mi][1], af[mi][2], af[mi][3],
                        stBase + aOff + (uint32_t)mi * (16 * ROWB) + kb);
            #pragma unroll
            for (int np = 0; np < 2; np++)
                ldsm_x4(bf[2*np][0], bf[2*np][1], bf[2*np+1][0], bf[2*np+1][1],
                        stBase + bOff + (uint32_t)np * (16 * ROWB) + kb);
            if (pf) {
                // one cp16 per thread per ks step (4 total per chunk)
                if (ks == 0) cp16(pfSb + cpSmA0, pfA);
                if (ks == 1) cp16(pfSb + cpSmB0, pfB);
                if (ks == 2) cp16(pfSb + cpSmA0 + cpSmStep, pfA + (size_t)64 * K);
                if (ks == 3) cp16(pfSb + cpSmB0 + cpSmStep, pfB + (size_t)64 * K);
            }
            #pragma unroll
            for (int mi = 0; mi < 2; mi++)
                #pragma unroll
                for (int ni = 0; ni < 4; ni++)
                    asm volatile(
                        "mma.sync.aligned.m16n8k16.row.col.f32.f16.f16.f32 "
                        "{%0,%1,%2,%3}, {%4,%5,%6,%7}, {%8,%9}, {%0,%1,%2,%3};"
                        : "+f"(acc[mi][ni][0]), "+f"(acc[mi][ni][1]),
                          "+f"(acc[mi][ni][2]), "+f"(acc[mi][ni][3])
                        : "r"(af[mi][0]), "r"(af[mi][1]), "r"(af[mi][2]), "r"(af[mi][3]),
                          "r"(bf[ni][0]), "r"(bf[ni][1]));
        }
        if (pf) asm volatile("cp.async.commit_group;");
        if (++stage == 3) stage = 0;
    }

    // -------- epilogue --------
    float* Cf = (float*)Cv;
    __half* Ch = (__half*)Cv;
    const __half* sgh = (const __half*)aux1;
    #pragma unroll
    for (int mi = 0; mi < 2; mi++) {
        const int rbase = m0 + wm * 32 + mi * 16 + g;
        #pragma unroll
        for (int ni = 0; ni < 4; ni++) {
            const int cc = n0 + wn * 32 + ni * 8 + t * 2;
            #pragma unroll
            for (int half_ = 0; half_ < 2; half_++) {
                const int r = rbase + half_ * 8;
                float v0 = acc[mi][ni][half_ * 2 + 0];
                float v1 = acc[mi][ni][half_ * 2 + 1];
                const size_t off = (size_t)r * N + cc;
                if (EPI == EPI_NONE) {
                    float2 o = {v0, v1};
                    *(float2*)(Cf + off) = o;
                } else if (EPI == EPI_SIG) {
                    float2 gb = *(const float2*)(aux0 + cc);
                    __half2 o = __floats2half2_rn(sigmf(v0 + gb.x), sigmf(v1 + gb.y));
                    *(uint32_t*)(Ch + off) = h2u(o);
                } else if (EPI == EPI_GATE) {
                    uint32_t su = *(const uint32_t*)(sgh + off);
                    float2 sg = __half22float2(*(__half2*)&su);
                    float2 xr = *(const float2*)(aux2 + off);
                    float2 o = {xr.x + sg.x * v0, xr.y + sg.y * v1};
                    *(float2*)(Cf + off) = o;
                } else if (EPI == EPI_SILU_H) {
                    float2 bb = *(const float2*)(aux0 + cc);
                    float t0 = v0 + bb.x, t1 = v1 + bb.y;
                    __half2 o = __floats2half2_rn(t0 * sigmf(t0), t1 * sigmf(t1));
                    *(uint32_t*)(Ch + off) = h2u(o);
                } else if (EPI == EPI_BIAS_RES) {
                    float2 bb = *(const float2*)(aux0 + cc);
                    float2 xr = *(const float2*)(aux2 + off);
                    float2 o = {xr.x + v0 + bb.x, xr.y + v1 + bb.y};
                    *(float2*)(Cf + off) = o;
                }
            }
        }
    }
}

// ---------------- depthwise causal conv + bias + SiLU + mem inject ----------
__global__ void __launch_bounds__(256)
ten_conv_mem_kernel(const float* __restrict__ beta0,
                    const float* __restrict__ pm,
                    const float* __restrict__ conv_w,
                    const float* __restrict__ conv_b,
                    const float* __restrict__ mem_gate,
                    float* __restrict__ bR, float* __restrict__ bI)
{
    const int b   = blockIdx.z;
    const int cg0 = blockIdx.y * 32;
    const int t0  = blockIdx.x * 64;
    __shared__ float sb[67][33];
    __shared__ float sp[64][33];
    const int tid = threadIdx.x;

    for (int i = tid; i < 67 * 32; i += 256) {
        const int r = i >> 5, c = i & 31;
        const int t = t0 + r - 3;
        sb[r][c] = (t >= 0) ? beta0[((size_t)(b * TT + t)) * C2K + cg0 + c] : 0.f;
    }
    for (int i = tid; i < 64 * 32; i += 256) {
        const int r = i >> 5, c = i & 31;
        sp[r][c] = pm[((size_t)(b * TT + t0 + r)) * C2K + cg0 + c];
    }
    __syncthreads();

    const float mg = 1.f / (1.f + expf(-mem_gate[0]));
    const int cl = tid >> 3;
    const int tg = (tid & 7) * 8;
    const int cglob = cg0 + cl;
    const float w0 = conv_w[cglob * 4 + 0];
    const float w1 = conv_w[cglob * 4 + 1];
    const float w2 = conv_w[cglob * 4 + 2];
    const float w3 = conv_w[cglob * 4 + 3];
    const float cb = conv_b[cglob];
    const int k = cglob & (KK - 1);
    float* dst = ((cglob < KK) ? bR : bI) + ((size_t)(b * KK + k)) * TT + t0 + tg;
    #pragma unroll
    for (int j = 0; j < 8; j++) {
        const int r = tg + j;
        float v = sb[r][cl] * w0 + sb[r + 1][cl] * w1 + sb[r + 2][cl] * w2 + sb[r + 3][cl] * w3 + cb;
        v = v * (1.f / (1.f + __expf(-v)));
        v += mg * sp[r][cl];
        dst[j] = v;
    }
}

// ---------------- complex first-order recurrence scan -----------------------
__global__ void __launch_bounds__(256)
ten_scan_kernel(const float* __restrict__ bR, const float* __restrict__ bI,
                const float* __restrict__ log_decay, const float* __restrict__ freq,
                float* __restrict__ cR, float* __restrict__ cI)
{
    const int bk = blockIdx.x;
    const int k = bk & (KK - 1);
    const float mag = 1.f / (1.f + expf(-log_decay[k]));
    float snf, csf;
    sincosf(freq[k], &snf, &csf);
    const float lr = mag * csf, li = mag * snf;
    const int tid = threadIdx.x;
    const size_t base = (size_t)bk * TT + tid * 16;

    float xr[16], xi[16];
    #pragma unroll
    for (int v = 0; v < 4; v++) {
        float4 a = *(const float4*)(bR + base + v * 4);
        xr[v*4+0] = a.x; xr[v*4+1] = a.y; xr[v*4+2] = a.z; xr[v*4+3] = a.w;
        float4 c = *(const float4*)(bI + base + v * 4);
        xi[v*4+0] = c.x; xi[v*4+1] = c.y; xi[v*4+2] = c.z; xi[v*4+3] = c.w;
    }

    float cr = 0.f, ci = 0.f;
    #pragma unroll
    for (int j = 0; j < 16; j++) {
        float nr = fmaf(lr, cr, fmaf(-li, ci, xr[j]));
        float ni = fmaf(lr, ci, fmaf( li, cr, xi[j]));
        cr = nr; ci = ni;
        xr[j] = cr; xi[j] = ci;
    }

    float fr = lr, fi = li;
    #pragma unroll
    for (int s = 0; s < 4; s++) {
        float nr = fr * fr - fi * fi;
        float ni = 2.f * fr * fi;
        fr = nr; fi = ni;
    }

    __shared__ float sgr[256], sgi[256], sor[256], soi[256];
    sgr[tid] = fr; sgi[tid] = fi; sor[tid] = cr; soi[tid] = ci;
    __syncthreads();
    for (int d = 1; d < 256; d <<= 1) {
        float ngr = 0.f, ngi = 0.f, nor_ = 0.f, noi_ = 0.f;
        if (tid >= d) {
            const float pgr = sgr[tid - d], pgi = sgi[tid - d];
            const float por = sor[tid - d], poi = soi[tid - d];
            const float gr = sgr[tid], gi = sgi[tid];
            const float orr = sor[tid], oii = soi[tid];
            ngr  = gr * pgr - gi * pgi;
            ngi  = gr * pgi + gi * pgr;
            nor_ = gr * por - gi * poi + orr;
            noi_ = gr * poi + gi * por + oii;
        }
        __syncthreads();
        if (tid >= d) { sgr[tid] = ngr; sgi[tid] = ngi; sor[tid] = nor_; soi[tid] = noi_; }
        __syncthreads();
    }
    const float pr = (tid > 0) ? sor[tid - 1] : 0.f;
    const float pi = (tid > 0) ? soi[tid - 1] : 0.f;

    float lpr = lr, lpi = li;
    #pragma unroll
    for (int j = 0; j < 16; j++) {
        xr[j] = fmaf(lpr, pr, fmaf(-lpi, pi, xr[j]));
        xi[j] = fmaf(lpr, pi, fmaf( lpi, pr, xi[j]));
        float nr = lpr * lr - lpi * li;
        float ni = lpr * li + lpi * lr;
        lpr = nr; lpi = ni;
    }
    #pragma unroll
    for (int v = 0; v < 4; v++) {
        float4 a = {xr[v*4+0], xr[v*4+1], xr[v*4+2], xr[v*4+3]};
        *(float4*)(cR + base + v * 4) = a;
        float4 c = {xi[v*4+0], xi[v*4+1], xi[v*4+2], xi[v*4+3]};
        *(float4*)(cI + base + v * 4) = c;
    }
}

// ---------------- coupling + transpose -> eig fp32 (output) + fp16 copy -----
__global__ void __launch_bounds__(256)
ten_coupling_kernel(const float* __restrict__ cR, const float* __restrict__ cI,
                    const float* __restrict__ coupling,
                    float* __restrict__ eig, __half* __restrict__ eig_h)
{
    const int b = blockIdx.z, h = blockIdx.y;
    const int t0 = blockIdx.x * 256;
    const int tid = threadIdx.x;
    __shared__ float sr[16][256];
    __shared__ float si[16][256];
    __shared__ float w[16][16];
    w[tid >> 4][tid & 15] = coupling[h * 256 + tid];
    #pragma unroll
    for (int kk = 0; kk < 16; kk++) {
        const size_t src = ((size_t)(b * KK + h * 16 + kk)) * TT + t0 + tid;
        sr[kk][tid] = cR[src];
        si[kk][tid] = cI[src];
    }
    __syncthreads();
    float orr[16], oii[16];
    #pragma unroll
    for (int j = 0; j < 16; j++) { orr[j] = 0.f; oii[j] = 0.f; }
    #pragma unroll
    for (int kk = 0; kk < 16; kk++) {
        const float vr = sr[kk][tid];
        const float vi = si[kk][tid];
        #pragma unroll
        for (int j = 0; j < 16; j++) {
            orr[j] = fmaf(w[j][kk], vr, orr[j]);
            oii[j] = fmaf(w[j][kk], vi, oii[j]);
        }
    }
    const size_t dst = ((size_t)(b * TT + t0 + tid)) * C2K + h * 16;
    #pragma unroll
    for (int j = 0; j < 16; j += 4) {
        float4 v = {orr[j], orr[j+1], orr[j+2], orr[j+3]};
        *(float4*)(eig + dst + j) = v;
        float4 u = {oii[j], oii[j+1], oii[j+2], oii[j+3]};
        *(float4*)(eig + dst + KK + j) = u;
        uint2 vv = {h2u(__floats2half2_rn(orr[j], orr[j+1])),
                    h2u(__floats2half2_rn(orr[j+2], orr[j+3]))};
        *(uint2*)(eig_h + dst + j) = vv;
        uint2 uu = {h2u(__floats2half2_rn(oii[j], oii[j+1])),
                    h2u(__floats2half2_rn(oii[j+2], oii[j+3]))};
        *(uint2*)(eig_h + dst + KK + j) = uu;
    }
}

// ---------------- launch -----------------------------------------------------
extern "C" void kernel_launch(void* const* d_in, const int* in_sizes, int n_in,
                              void* d_out, int out_size)
{
    const float* x          = (const float*)d_in[0];
    const float* prev_eig   = (const float*)d_in[1];
    const float* in_proj_w  = (const float*)d_in[2];
    const float* conv_w     = (const float*)d_in[3];
    const float* conv_b     = (const float*)d_in[4];
    const float* mem_gate   = (const float*)d_in[5];
    const float* mem_proj_w = (const float*)d_in[6];
    const float* log_decay  = (const float*)d_in[7];
    const float* frequency  = (const float*)d_in[8];
    const float* coupling   = (const float*)d_in[9];
    const float* out_proj_w = (const float*)d_in[10];
    const float* gate_w     = (const float*)d_in[11];
    const float* gate_b     = (const float*)d_in[12];
    const float* mlp_w1     = (const float*)d_in[13];
    const float* mlp_b1     = (const float*)d_in[14];
    const float* mlp_w2     = (const float*)d_in[15];
    const float* mlp_b2     = (const float*)d_in[16];
    const float* n1_g       = (const float*)d_in[17];
    const float* n1_b       = (const float*)d_in[18];
    const float* n2_g       = (const float*)d_in[19];
    const float* n2_b       = (const float*)d_in[20];

    float* out_x2  = (float*)d_out;
    float* out_eig = out_x2 + (size_t)NT * DD;

    __half *xn_h, *y_h, *h1_h, *eig_h, *pe_h, *sig_h, *wh;
    float *beta0, *pm, *bRp, *bIp, *cRp, *cIp, *x1;
    cudaGetSymbolAddress((void**)&xn_h,  g_xn_h);
    cudaGetSymbolAddress((void**)&y_h,   g_y_h);
    cudaGetSymbolAddress((void**)&h1_h,  g_h1_h);
    cudaGetSymbolAddress((void**)&eig_h, g_eig_h);
    cudaGetSymbolAddress((void**)&pe_h,  g_pe_h);
    cudaGetSymbolAddress((void**)&sig_h, g_sig_h);
    cudaGetSymbolAddress((void**)&wh,    g_wh);
    cudaGetSymbolAddress((void**)&beta0, g_beta0);
    cudaGetSymbolAddress((void**)&pm,    g_pm);
    cudaGetSymbolAddress((void**)&bRp,   g_bR);
    cudaGetSymbolAddress((void**)&bIp,   g_bI);
    cudaGetSymbolAddress((void**)&cRp,   g_cR);
    cudaGetSymbolAddress((void**)&cIp,   g_cI);
    cudaGetSymbolAddress((void**)&x1,    g_x1);

    cudaFuncSetAttribute(mma_gemm<EPI_NONE>,     cudaFuncAttributeMaxDynamicSharedMemorySize, GEMM_SMEM);
    cudaFuncSetAttribute(mma_gemm<EPI_SIG>,      cudaFuncAttributeMaxDynamicSharedMemorySize, GEMM_SMEM);
    cudaFuncSetAttribute(mma_gemm<EPI_GATE>,     cudaFuncAttributeMaxDynamicSharedMemorySize, GEMM_SMEM);
    cudaFuncSetAttribute(mma_gemm<EPI_SILU_H>,   cudaFuncAttributeMaxDynamicSharedMemorySize, GEMM_SMEM);
    cudaFuncSetAttribute(mma_gemm<EPI_BIAS_RES>, cudaFuncAttributeMaxDynamicSharedMemorySize, GEMM_SMEM);

    // one-time stream/event handles (host objects only)
    static cudaStream_t s1 = nullptr;
    static cudaEvent_t evStart = nullptr, evCvt = nullptr, evLN1 = nullptr,
                       evPm = nullptr, evCoup = nullptr;
    if (s1 == nullptr) {
        cudaStreamCreateWithFlags(&s1, cudaStreamNonBlocking);
        cudaEventCreateWithFlags(&evStart, cudaEventDisableTiming);
        cudaEventCreateWithFlags(&evCvt,   cudaEventDisableTiming);
        cudaEventCreateWithFlags(&evLN1,   cudaEventDisableTiming);
        cudaEventCreateWithFlags(&evPm,    cudaEventDisableTiming);
        cudaEventCreateWithFlags(&evCoup,  cudaEventDisableTiming);
    }

    cudaEventRecord(evStart, 0);
    cudaStreamWaitEvent(s1, evStart, 0);

    // ---- s1 branch: LN1 ----
    ten_ln_kernel<<<NT, 256, 0, s1>>>(x, n1_g, n1_b, xn_h);
    cudaEventRecord(evLN1, s1);

    // ---- s0: weight conversion ----
    CvtArgs ca;
    ca.src[0] = in_proj_w;  ca.dst[0] = wh + W_INPROJ;  ca.n8[0] = (int)((size_t)C2K * DD / 8);
    ca.src[1] = mem_proj_w; ca.dst[1] = wh + W_MEMPROJ; ca.n8[1] = (int)((size_t)C2K * C2K / 8);
    ca.src[2] = out_proj_w; ca.dst[2] = wh + W_OUTPROJ; ca.n8[2] = (int)((size_t)DD * C2K / 8);
    ca.src[3] = gate_w;     ca.dst[3] = wh + W_GATE;    ca.n8[3] = (int)((size_t)DD * DD / 8);
    ca.src[4] = mlp_w1;     ca.dst[4] = wh + W_MLP1;    ca.n8[4] = (int)((size_t)MM * DD / 8);
    ca.src[5] = mlp_w2;     ca.dst[5] = wh + W_MLP2;    ca.n8[5] = (int)((size_t)DD * MM / 8);
    ca.src[6] = prev_eig;   ca.dst[6] = pe_h;           ca.n8[6] = (int)((size_t)NT * C2K / 8);
    cvt_all_kernel<<<dim3(2048, 7), 256>>>(ca);
    cudaEventRecord(evCvt, 0);

    // ---- s0: pm GEMM ----
    mma_gemm<EPI_NONE><<<dim3(C2K/128, NT/128), 512, GEMM_SMEM>>>(
        pe_h, wh + W_MEMPROJ, pm, NT, C2K, C2K, nullptr, nullptr, nullptr);
    cudaEventRecord(evPm, 0);

    // ---- s1: in_proj ----
    cudaStreamWaitEvent(s1, evCvt, 0);
    mma_gemm<EPI_NONE><<<dim3(C2K/128, NT/128), 512, GEMM_SMEM, s1>>>(
        xn_h, wh + W_INPROJ, beta0, NT, C2K, DD, nullptr, nullptr, nullptr);

    // ---- s0: gate GEMM ----
    cudaStreamWaitEvent(0, evLN1, 0);
    mma_gemm<EPI_SIG><<<dim3(DD/128, NT/128), 512, GEMM_SMEM>>>(
        xn_h, wh + W_GATE, sig_h, NT, DD, DD, gate_b, nullptr, nullptr);

    // ---- s1: conv -> scan -> coupling ----
    cudaStreamWaitEvent(s1, evPm, 0);
    ten_conv_mem_kernel<<<dim3(TT/64, C2K/32, BB), 256, 0, s1>>>(
        beta0, pm, conv_w, conv_b, mem_gate, bRp, bIp);
    ten_scan_kernel<<<BB * KK, 256, 0, s1>>>(bRp, bIp, log_decay, frequency, cRp, cIp);
    ten_coupling_kernel<<<dim3(TT/256, HH, BB), 256, 0, s1>>>(cRp, cIp, coupling, out_eig, eig_h);
    cudaEventRecord(evCoup, s1);

    // ---- join: out_proj ----
    cudaStreamWaitEvent(0, evCoup, 0);
    mma_gemm<EPI_GATE><<<dim3(DD/128, NT/128), 512, GEMM_SMEM>>>(
        eig_h, wh + W_OUTPROJ, x1, NT, DD, C2K, nullptr, sig_h, x);

    // ---- s0 tail: LN2, MLP ----
    ten_ln_kernel<<<NT, 256>>>(x1, n2_g, n2_b, y_h);
    mma_gemm<EPI_SILU_H><<<dim3(MM/128, NT/128), 512, GEMM_SMEM>>>(
        y_h, wh + W_MLP1, h1_h, NT, MM, DD, mlp_b1, nullptr, nullptr);
    mma_gemm<EPI_BIAS_RES><<<dim3(DD/128, NT/128), 512, GEMM_SMEM>>>(
        h1_h, wh + W_MLP2, out_x2, NT, DD, MM, mlp_b2, nullptr, x1);
}

// round 12
// speedup vs baseline: 1.0229x; 1.0229x over previous
#include <cuda_runtime.h>
#include <cuda_fp16.h>
#include <math.h>
#include <stdint.h>

// ---------------- problem constants ----------------
#define BB 4
#define TT 4096
#define DD 1024
#define KK 128
#define HH 8
#define KER 4
#define MM 4096          // mlp hidden
#define C2K 256          // 2*K
#define NT (BB*TT)       // 16384 rows

// ---------------- scratch (static device, no allocs) ----------------
__device__ __half g_xn_h[(size_t)NT*DD];     // LN1 out fp16
__device__ __half g_y_h[(size_t)NT*DD];      // LN2 out fp16
__device__ __half g_h1_h[(size_t)NT*MM];     // mlp mid fp16
__device__ __half g_eig_h[(size_t)NT*C2K];   // fp16 copy of eig
__device__ __half g_pe_h[(size_t)NT*C2K];    // fp16 prev_eig
__device__ __half g_sig_h[(size_t)NT*DD];    // sigmoid gate fp16
__device__ __half g_beta0h[(size_t)NT*C2K];  // in_proj out fp16
__device__ __half g_pmh[(size_t)NT*C2K];     // mem_proj out fp16
__device__ float  g_bR[(size_t)BB*KK*TT];
__device__ float  g_bI[(size_t)BB*KK*TT];
__device__ float  g_cR[(size_t)BB*KK*TT];
__device__ float  g_cI[(size_t)BB*KK*TT];
__device__ float  g_x1[(size_t)NT*DD];
// fp16 weights, packed
#define W_INPROJ  0
#define W_MEMPROJ (W_INPROJ + C2K*DD)
#define W_OUTPROJ (W_MEMPROJ + C2K*C2K)
#define W_GATE    (W_OUTPROJ + DD*C2K)
#define W_MLP1    (W_GATE + DD*DD)
#define W_MLP2    (W_MLP1 + (size_t)MM*DD)
#define W_TOTAL   (W_MLP2 + (size_t)DD*MM)
__device__ __half g_wh[W_TOTAL];

__device__ __forceinline__ float sigmf(float x) { return 1.f / (1.f + __expf(-x)); }
__device__ __forceinline__ uint32_t smem_u32(const void* p) {
    uint32_t a;
    asm("{ .reg .u64 t; cvta.to.shared.u64 t, %1; cvt.u32.u64 %0, t; }" : "=r"(a) : "l"(p));
    return a;
}
__device__ __forceinline__ void cp16(uint32_t s, const void* g) {
    asm volatile("cp.async.cg.shared.global [%0], [%1], 16;" :: "r"(s), "l"(g));
}
__device__ __forceinline__ uint32_t h2u(__half2 h) { return *(uint32_t*)&h; }
__device__ __forceinline__ void ldsm_x4(uint32_t& r0, uint32_t& r1, uint32_t& r2, uint32_t& r3,
                                        uint32_t addr) {
    asm volatile("ldmatrix.sync.aligned.m8n8.x4.shared.b16 {%0,%1,%2,%3}, [%4];"
                 : "=r"(r0), "=r"(r1), "=r"(r2), "=r"(r3) : "r"(addr));
}

// ============================ batched fp32 -> fp16 ============================
struct CvtArgs {
    const float* src[7];
    __half* dst[7];
    int n8[7];
};
__global__ void cvt_all_kernel(CvtArgs a)
{
    const int seg = blockIdx.y;
    const int i = blockIdx.x * blockDim.x + threadIdx.x;
    if (i < a.n8[seg]) {
        const float4* s4 = (const float4*)a.src[seg] + 2 * (size_t)i;
        float4 p = s4[0], q = s4[1];
        uint4 o = {h2u(__floats2half2_rn(p.x, p.y)), h2u(__floats2half2_rn(p.z, p.w)),
                   h2u(__floats2half2_rn(q.x, q.y)), h2u(__floats2half2_rn(q.z, q.w))};
        ((uint4*)a.dst[seg])[i] = o;
    }
}

// ============================ LayerNorm -> fp16 out ============================
__global__ void ten_ln_kernel(const float* __restrict__ x,
                              const float* __restrict__ gw,
                              const float* __restrict__ bw,
                              __half* __restrict__ yh)
{
    const int row = blockIdx.x;
    const int tid = threadIdx.x;
    const float4* xr = (const float4*)(x + (size_t)row * DD);
    float4 v = xr[tid];
    float s = v.x + v.y + v.z + v.w;
    float q = v.x*v.x + v.y*v.y + v.z*v.z + v.w*v.w;
    #pragma unroll
    for (int o = 16; o > 0; o >>= 1) {
        s += __shfl_xor_sync(0xffffffffu, s, o);
        q += __shfl_xor_sync(0xffffffffu, q, o);
    }
    __shared__ float ss[8], sq[8];
    const int w = tid >> 5, l = tid & 31;
    if (l == 0) { ss[w] = s; sq[w] = q; }
    __syncthreads();
    float st = 0.f, qt = 0.f;
    #pragma unroll
    for (int i = 0; i < 8; i++) { st += ss[i]; qt += sq[i]; }
    const float mean = st * (1.f / DD);
    const float var  = qt * (1.f / DD) - mean * mean;
    const float rstd = rsqrtf(var + 1e-5f);
    float4 g4 = ((const float4*)gw)[tid];
    float4 b4 = ((const float4*)bw)[tid];
    float ox = (v.x - mean) * rstd * g4.x + b4.x;
    float oy = (v.y - mean) * rstd * g4.y + b4.y;
    float oz = (v.z - mean) * rstd * g4.z + b4.z;
    float ow = (v.w - mean) * rstd * g4.w + b4.w;
    uint2 ov = {h2u(__floats2half2_rn(ox, oy)), h2u(__floats2half2_rn(oz, ow))};
    ((uint2*)(yh + (size_t)row * DD))[tid] = ov;
}

// ============================ fp16 mma.sync GEMM ============================
// block 128x128, BK=64 halves, 3-stage cp.async ring, 8 warps (2x4),
// warp tile 64x32, cp.async spread across ks loop, 2 CTAs/SM.
enum { EPI_NONE = 0, EPI_SIG = 1, EPI_GATE = 2, EPI_SILU_H = 3, EPI_BIAS_RES = 4, EPI_H = 5 };

#define ASTR 36                    // b32 per SMEM row (32 data + 4 pad)
#define ROWB (ASTR*4)              // 144 bytes per row
#define A_B32 (128*ASTR)
#define B_B32 (128*ASTR)
#define ST_B32 (A_B32 + B_B32)     // 9216 b32
#define GEMM_SMEM (3*ST_B32*4)     // 110592 B

template<int EPI>
__global__ void __launch_bounds__(256, 2)
mma_gemm(const __half* __restrict__ A, const __half* __restrict__ B, void* Cv,
         int M, int N, int K,
         const float* __restrict__ aux0, const void* __restrict__ aux1,
         const float* __restrict__ aux2)
{
    extern __shared__ uint32_t smu[];
    const uint32_t sm_base = smem_u32(smu);
    const int tid = threadIdx.x;
    const int lane = tid & 31, wid = tid >> 5;
    const int wm = wid >> 2, wn = wid & 3;          // 2 x 4 warp grid
    const int m0 = blockIdx.y * 128, n0 = blockIdx.x * 128;
    const int nchunk = K >> 6;
    const int g = lane >> 2, t = lane & 3;

    const __half* Ag = A + (size_t)m0 * K;
    const __half* Bg = B + (size_t)n0 * K;

    const int r0 = tid >> 3;            // 0..31
    const int u  = tid & 7;             // 0..7
    const uint32_t cpSmA0 = (uint32_t)(r0 * ASTR + u * 4) * 4;
    const uint32_t cpSmB0 = (uint32_t)(A_B32 + r0 * ASTR + u * 4) * 4;
    const uint32_t cpSmStep = (uint32_t)(32 * ASTR) * 4;

    auto load_stage = [&](int s, int c) {
        const uint32_t sb = sm_base + (uint32_t)(s * ST_B32) * 4;
        const __half* ac = Ag + (size_t)c * 64;
        const __half* bc = Bg + (size_t)c * 64;
        #pragma unroll
        for (int j = 0; j < 4; j++) {
            const int r = r0 + j * 32;
            cp16(sb + cpSmA0 + j * cpSmStep, ac + (size_t)r * K + u * 8);
            cp16(sb + cpSmB0 + j * cpSmStep, bc + (size_t)r * K + u * 8);
        }
        asm volatile("cp.async.commit_group;");
    };

    float acc[4][4][4];
    #pragma unroll
    for (int mi = 0; mi < 4; mi++)
        #pragma unroll
        for (int ni = 0; ni < 4; ni++)
            #pragma unroll
            for (int q = 0; q < 4; q++) acc[mi][ni][q] = 0.f;

    load_stage(0, 0);
    if (1 < nchunk) load_stage(1, 1);

    const uint32_t aOff = (uint32_t)(wm * 64 + (lane & 15)) * ROWB + (uint32_t)(lane >> 4) * 16;
    const uint32_t bOff = (uint32_t)A_B32 * 4 +
        (uint32_t)(wn * 32 + (lane & 7) + ((lane >> 4) & 1) * 8) * ROWB +
        (uint32_t)((lane >> 3) & 1) * 16;

    int stage = 0;
    for (int i = 0; i < nchunk; i++) {
        if (i == nchunk - 1) asm volatile("cp.async.wait_group 0;" ::: "memory");
        else                 asm volatile("cp.async.wait_group 1;" ::: "memory");
        __syncthreads();

        const bool pf = (i + 2 < nchunk);
        int ns = stage + 2; if (ns >= 3) ns -= 3;
        const uint32_t pfSb = sm_base + (uint32_t)(ns * ST_B32) * 4;
        const __half* pfA = Ag + (size_t)(i + 2) * 64 + (size_t)r0 * K + u * 8;
        const __half* pfB = Bg + (size_t)(i + 2) * 64 + (size_t)r0 * K + u * 8;

        const uint32_t stBase = sm_base + (uint32_t)(stage * ST_B32) * 4;
        #pragma unroll
        for (int ks = 0; ks < 4; ks++) {
            const uint32_t kb = (uint32_t)ks * 32;
            uint32_t af[4][4], bf[4][2];
            #pragma unroll
            for (int mi = 0; mi < 4; mi++)
                ldsm_x4(af[mi][0], af[mi][1], af[mi][2], af[mi][3],
                        stBase + aOff + (uint32_t)mi * (16 * ROWB) + kb);
            #pragma unroll
            for (int np = 0; np < 2; np++)
                ldsm_x4(bf[2*np][0], bf[2*np][1], bf[2*np+1][0], bf[2*np+1][1],
                        stBase + bOff + (uint32_t)np * (16 * ROWB) + kb);
            if (pf) {
                cp16(pfSb + cpSmA0 + (uint32_t)ks * cpSmStep, pfA + (size_t)(ks * 32) * K);
                cp16(pfSb + cpSmB0 + (uint32_t)ks * cpSmStep, pfB + (size_t)(ks * 32) * K);
            }
            #pragma unroll
            for (int mi = 0; mi < 4; mi++)
                #pragma unroll
                for (int ni = 0; ni < 4; ni++)
                    asm volatile(
                        "mma.sync.aligned.m16n8k16.row.col.f32.f16.f16.f32 "
                        "{%0,%1,%2,%3}, {%4,%5,%6,%7}, {%8,%9}, {%0,%1,%2,%3};"
                        : "+f"(acc[mi][ni][0]), "+f"(acc[mi][ni][1]),
                          "+f"(acc[mi][ni][2]), "+f"(acc[mi][ni][3])
                        : "r"(af[mi][0]), "r"(af[mi][1]), "r"(af[mi][2]), "r"(af[mi][3]),
                          "r"(bf[ni][0]), "r"(bf[ni][1]));
        }
        if (pf) asm volatile("cp.async.commit_group;");
        if (++stage == 3) stage = 0;
    }

    // -------- epilogue --------
    float* Cf = (float*)Cv;
    __half* Ch = (__half*)Cv;
    const __half* sgh = (const __half*)aux1;
    #pragma unroll
    for (int mi = 0; mi < 4; mi++) {
        const int rbase = m0 + wm * 64 + mi * 16 + g;
        #pragma unroll
        for (int ni = 0; ni < 4; ni++) {
            const int cc = n0 + wn * 32 + ni * 8 + t * 2;
            #pragma unroll
            for (int half_ = 0; half_ < 2; half_++) {
                const int r = rbase + half_ * 8;
                float v0 = acc[mi][ni][half_ * 2 + 0];
                float v1 = acc[mi][ni][half_ * 2 + 1];
                const size_t off = (size_t)r * N + cc;
                if (EPI == EPI_NONE) {
                    float2 o = {v0, v1};
                    *(float2*)(Cf + off) = o;
                } else if (EPI == EPI_H) {
                    __half2 o = __floats2half2_rn(v0, v1);
                    *(uint32_t*)(Ch + off) = h2u(o);
                } else if (EPI == EPI_SIG) {
                    float2 gb = *(const float2*)(aux0 + cc);
                    __half2 o = __floats2half2_rn(sigmf(v0 + gb.x), sigmf(v1 + gb.y));
                    *(uint32_t*)(Ch + off) = h2u(o);
                } else if (EPI == EPI_GATE) {
                    uint32_t su = *(const uint32_t*)(sgh + off);
                    float2 sg = __half22float2(*(__half2*)&su);
                    float2 xr = *(const float2*)(aux2 + off);
                    float2 o = {xr.x + sg.x * v0, xr.y + sg.y * v1};
                    *(float2*)(Cf + off) = o;
                } else if (EPI == EPI_SILU_H) {
                    float2 bb = *(const float2*)(aux0 + cc);
                    float t0 = v0 + bb.x, t1 = v1 + bb.y;
                    __half2 o = __floats2half2_rn(t0 * sigmf(t0), t1 * sigmf(t1));
                    *(uint32_t*)(Ch + off) = h2u(o);
                } else if (EPI == EPI_BIAS_RES) {
                    float2 bb = *(const float2*)(aux0 + cc);
                    float2 xr = *(const float2*)(aux2 + off);
                    float2 o = {xr.x + v0 + bb.x, xr.y + v1 + bb.y};
                    *(float2*)(Cf + off) = o;
                }
            }
        }
    }
}

// ---------------- depthwise causal conv + bias + SiLU + mem inject (fp16 in) --
__global__ void __launch_bounds__(256)
ten_conv_mem_kernel(const __half* __restrict__ beta0,
                    const __half* __restrict__ pm,
                    const float* __restrict__ conv_w,
                    const float* __restrict__ conv_b,
                    const float* __restrict__ mem_gate,
                    float* __restrict__ bR, float* __restrict__ bI)
{
    const int b   = blockIdx.z;
    const int cg0 = blockIdx.y * 32;
    const int t0  = blockIdx.x * 64;
    __shared__ float sb[67][33];
    __shared__ float sp[64][33];
    const int tid = threadIdx.x;

    for (int i = tid; i < 67 * 32; i += 256) {
        const int r = i >> 5, c = i & 31;
        const int t = t0 + r - 3;
        sb[r][c] = (t >= 0) ? __half2float(beta0[((size_t)(b * TT + t)) * C2K + cg0 + c]) : 0.f;
    }
    for (int i = tid; i < 64 * 32; i += 256) {
        const int r = i >> 5, c = i & 31;
        sp[r][c] = __half2float(pm[((size_t)(b * TT + t0 + r)) * C2K + cg0 + c]);
    }
    __syncthreads();

    const float mg = 1.f / (1.f + expf(-mem_gate[0]));
    const int cl = tid >> 3;
    const int tg = (tid & 7) * 8;
    const int cglob = cg0 + cl;
    const float w0 = conv_w[cglob * 4 + 0];
    const float w1 = conv_w[cglob * 4 + 1];
    const float w2 = conv_w[cglob * 4 + 2];
    const float w3 = conv_w[cglob * 4 + 3];
    const float cb = conv_b[cglob];
    const int k = cglob & (KK - 1);
    float* dst = ((cglob < KK) ? bR : bI) + ((size_t)(b * KK + k)) * TT + t0 + tg;
    #pragma unroll
    for (int j = 0; j < 8; j++) {
        const int r = tg + j;
        float v = sb[r][cl] * w0 + sb[r + 1][cl] * w1 + sb[r + 2][cl] * w2 + sb[r + 3][cl] * w3 + cb;
        v = v * (1.f / (1.f + __expf(-v)));
        v += mg * sp[r][cl];
        dst[j] = v;
    }
}

// ---------------- complex first-order recurrence scan -----------------------
__global__ void __launch_bounds__(256)
ten_scan_kernel(const float* __restrict__ bR, const float* __restrict__ bI,
                const float* __restrict__ log_decay, const float* __restrict__ freq,
                float* __restrict__ cR, float* __restrict__ cI)
{
    const int bk = blockIdx.x;
    const int k = bk & (KK - 1);
    const float mag = 1.f / (1.f + expf(-log_decay[k]));
    float snf, csf;
    sincosf(freq[k], &snf, &csf);
    const float lr = mag * csf, li = mag * snf;
    const int tid = threadIdx.x;
    const size_t base = (size_t)bk * TT + tid * 16;

    float xr[16], xi[16];
    #pragma unroll
    for (int v = 0; v < 4; v++) {
        float4 a = *(const float4*)(bR + base + v * 4);
        xr[v*4+0] = a.x; xr[v*4+1] = a.y; xr[v*4+2] = a.z; xr[v*4+3] = a.w;
        float4 c = *(const float4*)(bI + base + v * 4);
        xi[v*4+0] = c.x; xi[v*4+1] = c.y; xi[v*4+2] = c.z; xi[v*4+3] = c.w;
    }

    float cr = 0.f, ci = 0.f;
    #pragma unroll
    for (int j = 0; j < 16; j++) {
        float nr = fmaf(lr, cr, fmaf(-li, ci, xr[j]));
        float ni = fmaf(lr, ci, fmaf( li, cr, xi[j]));
        cr = nr; ci = ni;
        xr[j] = cr; xi[j] = ci;
    }

    float fr = lr, fi = li;
    #pragma unroll
    for (int s = 0; s < 4; s++) {
        float nr = fr * fr - fi * fi;
        float ni = 2.f * fr * fi;
        fr = nr; fi = ni;
    }

    __shared__ float sgr[256], sgi[256], sor[256], soi[256];
    sgr[tid] = fr; sgi[tid] = fi; sor[tid] = cr; soi[tid] = ci;
    __syncthreads();
    for (int d = 1; d < 256; d <<= 1) {
        float ngr = 0.f, ngi = 0.f, nor_ = 0.f, noi_ = 0.f;
        if (tid >= d) {
            const float pgr = sgr[tid - d], pgi = sgi[tid - d];
            const float por = sor[tid - d], poi = soi[tid - d];
            const float gr = sgr[tid], gi = sgi[tid];
            const float orr = sor[tid], oii = soi[tid];
            ngr  = gr * pgr - gi * pgi;
            ngi  = gr * pgi + gi * pgr;
            nor_ = gr * por - gi * poi + orr;
            noi_ = gr * poi + gi * por + oii;
        }
        __syncthreads();
        if (tid >= d) { sgr[tid] = ngr; sgi[tid] = ngi; sor[tid] = nor_; soi[tid] = noi_; }
        __syncthreads();
    }
    const float pr = (tid > 0) ? sor[tid - 1] : 0.f;
    const float pi = (tid > 0) ? soi[tid - 1] : 0.f;

    float lpr = lr, lpi = li;
    #pragma unroll
    for (int j = 0; j < 16; j++) {
        xr[j] = fmaf(lpr, pr, fmaf(-lpi, pi, xr[j]));
        xi[j] = fmaf(lpr, pi, fmaf( lpi, pr, xi[j]));
        float nr = lpr * lr - lpi * li;
        float ni = lpr * li + lpi * lr;
        lpr = nr; lpi = ni;
    }
    #pragma unroll
    for (int v = 0; v < 4; v++) {
        float4 a = {xr[v*4+0], xr[v*4+1], xr[v*4+2], xr[v*4+3]};
        *(float4*)(cR + base + v * 4) = a;
        float4 c = {xi[v*4+0], xi[v*4+1], xi[v*4+2], xi[v*4+3]};
        *(float4*)(cI + base + v * 4) = c;
    }
}

// ---------------- coupling + transpose -> eig fp32 (output) + fp16 copy -----
__global__ void __launch_bounds__(256)
ten_coupling_kernel(const float* __restrict__ cR, const float* __restrict__ cI,
                    const float* __restrict__ coupling,
                    float* __restrict__ eig, __half* __restrict__ eig_h)
{
    const int b = blockIdx.z, h = blockIdx.y;
    const int t0 = blockIdx.x * 256;
    const int tid = threadIdx.x;
    __shared__ float sr[16][256];
    __shared__ float si[16][256];
    __shared__ float w[16][16];
    w[tid >> 4][tid & 15] = coupling[h * 256 + tid];
    #pragma unroll
    for (int kk = 0; kk < 16; kk++) {
        const size_t src = ((size_t)(b * KK + h * 16 + kk)) * TT + t0 + tid;
        sr[kk][tid] = cR[src];
        si[kk][tid] = cI[src];
    }
    __syncthreads();
    float orr[16], oii[16];
    #pragma unroll
    for (int j = 0; j < 16; j++) { orr[j] = 0.f; oii[j] = 0.f; }
    #pragma unroll
    for (int kk = 0; kk < 16; kk++) {
        const float vr = sr[kk][tid];
        const float vi = si[kk][tid];
        #pragma unroll
        for (int j = 0; j < 16; j++) {
            orr[j] = fmaf(w[j][kk], vr, orr[j]);
            oii[j] = fmaf(w[j][kk], vi, oii[j]);
        }
    }
    const size_t dst = ((size_t)(b * TT + t0 + tid)) * C2K + h * 16;
    #pragma unroll
    for (int j = 0; j < 16; j += 4) {
        float4 v = {orr[j], orr[j+1], orr[j+2], orr[j+3]};
        *(float4*)(eig + dst + j) = v;
        float4 u = {oii[j], oii[j+1], oii[j+2], oii[j+3]};
        *(float4*)(eig + dst + KK + j) = u;
        uint2 vv = {h2u(__floats2half2_rn(orr[j], orr[j+1])),
                    h2u(__floats2half2_rn(orr[j+2], orr[j+3]))};
        *(uint2*)(eig_h + dst + j) = vv;
        uint2 uu = {h2u(__floats2half2_rn(oii[j], oii[j+1])),
                    h2u(__floats2half2_rn(oii[j+2], oii[j+3]))};
        *(uint2*)(eig_h + dst + KK + j) = uu;
    }
}

// ---------------- launch -----------------------------------------------------
extern "C" void kernel_launch(void* const* d_in, const int* in_sizes, int n_in,
                              void* d_out, int out_size)
{
    const float* x          = (const float*)d_in[0];
    const float* prev_eig   = (const float*)d_in[1];
    const float* in_proj_w  = (const float*)d_in[2];
    const float* conv_w     = (const float*)d_in[3];
    const float* conv_b     = (const float*)d_in[4];
    const float* mem_gate   = (const float*)d_in[5];
    const float* mem_proj_w = (const float*)d_in[6];
    const float* log_decay  = (const float*)d_in[7];
    const float* frequency  = (const float*)d_in[8];
    const float* coupling   = (const float*)d_in[9];
    const float* out_proj_w = (const float*)d_in[10];
    const float* gate_w     = (const float*)d_in[11];
    const float* gate_b     = (const float*)d_in[12];
    const float* mlp_w1     = (const float*)d_in[13];
    const float* mlp_b1     = (const float*)d_in[14];
    const float* mlp_w2     = (const float*)d_in[15];
    const float* mlp_b2     = (const float*)d_in[16];
    const float* n1_g       = (const float*)d_in[17];
    const float* n1_b       = (const float*)d_in[18];
    const float* n2_g       = (const float*)d_in[19];
    const float* n2_b       = (const float*)d_in[20];

    float* out_x2  = (float*)d_out;
    float* out_eig = out_x2 + (size_t)NT * DD;

    __half *xn_h, *y_h, *h1_h, *eig_h, *pe_h, *sig_h, *wh, *beta0h, *pmh;
    float *bRp, *bIp, *cRp, *cIp, *x1;
    cudaGetSymbolAddress((void**)&xn_h,   g_xn_h);
    cudaGetSymbolAddress((void**)&y_h,    g_y_h);
    cudaGetSymbolAddress((void**)&h1_h,   g_h1_h);
    cudaGetSymbolAddress((void**)&eig_h,  g_eig_h);
    cudaGetSymbolAddress((void**)&pe_h,   g_pe_h);
    cudaGetSymbolAddress((void**)&sig_h,  g_sig_h);
    cudaGetSymbolAddress((void**)&wh,     g_wh);
    cudaGetSymbolAddress((void**)&beta0h, g_beta0h);
    cudaGetSymbolAddress((void**)&pmh,    g_pmh);
    cudaGetSymbolAddress((void**)&bRp,    g_bR);
    cudaGetSymbolAddress((void**)&bIp,    g_bI);
    cudaGetSymbolAddress((void**)&cRp,    g_cR);
    cudaGetSymbolAddress((void**)&cIp,    g_cI);
    cudaGetSymbolAddress((void**)&x1,     g_x1);

    cudaFuncSetAttribute(mma_gemm<EPI_NONE>,     cudaFuncAttributeMaxDynamicSharedMemorySize, GEMM_SMEM);
    cudaFuncSetAttribute(mma_gemm<EPI_H>,        cudaFuncAttributeMaxDynamicSharedMemorySize, GEMM_SMEM);
    cudaFuncSetAttribute(mma_gemm<EPI_SIG>,      cudaFuncAttributeMaxDynamicSharedMemorySize, GEMM_SMEM);
    cudaFuncSetAttribute(mma_gemm<EPI_GATE>,     cudaFuncAttributeMaxDynamicSharedMemorySize, GEMM_SMEM);
    cudaFuncSetAttribute(mma_gemm<EPI_SILU_H>,   cudaFuncAttributeMaxDynamicSharedMemorySize, GEMM_SMEM);
    cudaFuncSetAttribute(mma_gemm<EPI_BIAS_RES>, cudaFuncAttributeMaxDynamicSharedMemorySize, GEMM_SMEM);

    // one-time stream/event handles (host objects only)
    static cudaStream_t s1 = nullptr;
    static cudaEvent_t evStart = nullptr, evCvt = nullptr, evLN1 = nullptr,
                       evCoup = nullptr;
    if (s1 == nullptr) {
        cudaStreamCreateWithFlags(&s1, cudaStreamNonBlocking);
        cudaEventCreateWithFlags(&evStart, cudaEventDisableTiming);
        cudaEventCreateWithFlags(&evCvt,   cudaEventDisableTiming);
        cudaEventCreateWithFlags(&evLN1,   cudaEventDisableTiming);
        cudaEventCreateWithFlags(&evCoup,  cudaEventDisableTiming);
    }

    cudaEventRecord(evStart, 0);
    cudaStreamWaitEvent(s1, evStart, 0);

    // ---- s1 branch: LN1 ----
    ten_ln_kernel<<<NT, 256, 0, s1>>>(x, n1_g, n1_b, xn_h);
    cudaEventRecord(evLN1, s1);

    // ---- s0: weight conversion ----
    CvtArgs ca;
    ca.src[0] = in_proj_w;  ca.dst[0] = wh + W_INPROJ;  ca.n8[0] = (int)((size_t)C2K * DD / 8);
    ca.src[1] = mem_proj_w; ca.dst[1] = wh + W_MEMPROJ; ca.n8[1] = (int)((size_t)C2K * C2K / 8);
    ca.src[2] = out_proj_w; ca.dst[2] = wh + W_OUTPROJ; ca.n8[2] = (int)((size_t)DD * C2K / 8);
    ca.src[3] = gate_w;     ca.dst[3] = wh + W_GATE;    ca.n8[3] = (int)((size_t)DD * DD / 8);
    ca.src[4] = mlp_w1;     ca.dst[4] = wh + W_MLP1;    ca.n8[4] = (int)((size_t)MM * DD / 8);
    ca.src[5] = mlp_w2;     ca.dst[5] = wh + W_MLP2;    ca.n8[5] = (int)((size_t)DD * MM / 8);
    ca.src[6] = prev_eig;   ca.dst[6] = pe_h;           ca.n8[6] = (int)((size_t)NT * C2K / 8);
    cvt_all_kernel<<<dim3(2048, 7), 256>>>(ca);
    cudaEventRecord(evCvt, 0);

    // ---- s0: gate GEMM first (largest independent work) ----
    cudaStreamWaitEvent(0, evLN1, 0);
    mma_gemm<EPI_SIG><<<dim3(DD/128, NT/128), 256, GEMM_SMEM>>>(
        xn_h, wh + W_GATE, sig_h, NT, DD, DD, gate_b, nullptr, nullptr);

    // ---- s1: in_proj -> pm -> conv -> scan -> coupling ----
    cudaStreamWaitEvent(s1, evCvt, 0);
    mma_gemm<EPI_H><<<dim3(C2K/128, NT/128), 256, GEMM_SMEM, s1>>>(
        xn_h, wh + W_INPROJ, beta0h, NT, C2K, DD, nullptr, nullptr, nullptr);
    mma_gemm<EPI_H><<<dim3(C2K/128, NT/128), 256, GEMM_SMEM, s1>>>(
        pe_h, wh + W_MEMPROJ, pmh, NT, C2K, C2K, nullptr, nullptr, nullptr);
    ten_conv_mem_kernel<<<dim3(TT/64, C2K/32, BB), 256, 0, s1>>>(
        beta0h, pmh, conv_w, conv_b, mem_gate, bRp, bIp);
    ten_scan_kernel<<<BB * KK, 256, 0, s1>>>(bRp, bIp, log_decay, frequency, cRp, cIp);
    ten_coupling_kernel<<<dim3(TT/256, HH, BB), 256, 0, s1>>>(cRp, cIp, coupling, out_eig, eig_h);
    cudaEventRecord(evCoup, s1);

    // ---- join: out_proj needs coupling (s1) + gate (s0) ----
    cudaStreamWaitEvent(0, evCoup, 0);
    mma_gemm<EPI_GATE><<<dim3(DD/128, NT/128), 256, GEMM_SMEM>>>(
        eig_h, wh + W_OUTPROJ, x1, NT, DD, C2K, nullptr, sig_h, x);

    // ---- s0 tail: LN2, MLP ----
    ten_ln_kernel<<<NT, 256>>>(x1, n2_g, n2_b, y_h);
    mma_gemm<EPI_SILU_H><<<dim3(MM/128, NT/128), 256, GEMM_SMEM>>>(
        y_h, wh + W_MLP1, h1_h, NT, MM, DD, mlp_b1, nullptr, nullptr);
    mma_gemm<EPI_BIAS_RES><<<dim3(DD/128, NT/128), 256, GEMM_SMEM>>>(
        h1_h, wh + W_MLP2, out_x2, NT, DD, MM, mlp_b2, nullptr, x1);
}